// round 11
// baseline (speedup 1.0000x reference)
#include <cuda_runtime.h>
#include <cstdint>
#include <cstddef>

// Problem dims (fixed)
#define BB 4
#define KSEQ 4096
#define DD 2048
#define M_TOTAL (BB * KSEQ)   // 16384

// Device scratch (__device__ globals per allocation rules)
__device__ float g_lam[(size_t)M_TOTAL * DD];   // 128 MB
__device__ float g_xr [(size_t)M_TOTAL * DD];   // 128 MB tf32-rounded x
__device__ float g_wr [(size_t)DD * DD];        // 16 MB  tf32-rounded W

// ---------------------------------------------------------------------------
// GEMM + bias + sigmoid via tf32 mma.sync m16n8k8 — EXACT R5 structure (the
// only measured-fast tensor config on this toolchain: 128x128x32, warp 64x32,
// 64 acc regs, launch_bounds(256,2), PAD=36 conflict-free scalar LDS) with ONE
// change: inputs pre-rounded to tf32 bits in gmem, so the inner loop loads raw
// uint32 fragments (no cvt.rna on the LDS->mma critical path; 64->40
// instrs per warp per ks-step). Numerically bit-identical to R5.
// ---------------------------------------------------------------------------
#define Bb 128            // block M
#define BN 128            // block N
#define BK 32             // block K
#define STAGES 3
#define PAD 36            // floats per smem row
#define A_ST_FLOATS (Bb * PAD)
#define B_ST_FLOATS (BN * PAD)
#define STAGE_FLOATS (A_ST_FLOATS + B_ST_FLOATS)
#define GEMM_SMEM (STAGES * STAGE_FLOATS * 4)     // 110592 B
#define GEMM_THREADS 256

__device__ __forceinline__ uint32_t smem_u32(const void* p) {
    uint32_t a;
    asm("{ .reg .u64 t; cvta.to.shared.u64 t, %1; cvt.u32.u64 %0, t; }" : "=r"(a) : "l"(p));
    return a;
}
__device__ __forceinline__ void cpa16(uint32_t dst, const void* src) {
    asm volatile("cp.async.cg.shared.global [%0], [%1], 16;" :: "r"(dst), "l"(src) : "memory");
}
#define CP_COMMIT() asm volatile("cp.async.commit_group;" ::: "memory")
#define CP_WAIT(n)  asm volatile("cp.async.wait_group %0;" :: "n"(n) : "memory")

__device__ __forceinline__ uint32_t f32_to_tf32(float v) {
    uint32_t r;
    asm("cvt.rna.tf32.f32 %0, %1;" : "=r"(r) : "f"(v));
    return r;
}
__device__ __forceinline__ float sigmoidf_fast(float z) {
    return 1.0f / (1.0f + __expf(-z));
}

// ---------------- pre-round fp32 -> tf32-representable fp32 -----------------
__global__ void round_kernel(const float* __restrict__ src,
                             float* __restrict__ dst, int n4) {
    int i = blockIdx.x * blockDim.x + threadIdx.x;
    int stride = gridDim.x * blockDim.x;
    for (; i < n4; i += stride) {
        float4 v = ((const float4*)src)[i];
        uint4 o;
        o.x = f32_to_tf32(v.x);
        o.y = f32_to_tf32(v.y);
        o.z = f32_to_tf32(v.z);
        o.w = f32_to_tf32(v.w);
        ((uint4*)dst)[i] = o;
    }
}

__global__ __launch_bounds__(GEMM_THREADS, 2)
void gemm_sigmoid_kernel(const float* __restrict__ A,      // xr [M, D] (tf32 bits)
                         const float* __restrict__ W,      // wr [E, D] (tf32 bits)
                         const float* __restrict__ bias) {
    extern __shared__ float smem[];
    const int tid  = threadIdx.x;
    const int warp = tid >> 5;
    const int lane = tid & 31;
    const int m0   = blockIdx.y * Bb;
    const int n0   = blockIdx.x * BN;
    const int wm   = (warp >> 2) * 64;     // 2 warp-rows
    const int wn   = (warp & 3) * 32;      // 4 warp-cols
    const int g    = lane >> 2;            // 0..7
    const int t4   = lane & 3;             // 0..3

    const int ldr = tid >> 3;              // cp.async row 0..31
    const int lds = tid & 7;               // 16B segment 0..7

    const uint32_t smem_base = smem_u32(smem);

    float acc[4][4][4];
#pragma unroll
    for (int i = 0; i < 4; i++)
#pragma unroll
        for (int j = 0; j < 4; j++)
#pragma unroll
            for (int c = 0; c < 4; c++) acc[i][j][c] = 0.0f;

    const int NKT = DD / BK;   // 64 chunks

    auto load_stage = [&](int kt, int s) {
        const int kk = kt * BK;
        const uint32_t sa = smem_base + (uint32_t)(s * STAGE_FLOATS) * 4u;
        const uint32_t sb = sa + (uint32_t)A_ST_FLOATS * 4u;
#pragma unroll
        for (int i = 0; i < 4; i++) {
            int row = i * 32 + ldr;        // 0..127
            cpa16(sa + (uint32_t)(row * PAD + lds * 4) * 4u,
                  A + (size_t)(m0 + row) * DD + kk + lds * 4);
        }
#pragma unroll
        for (int i = 0; i < 4; i++) {
            int row = i * 32 + ldr;
            cpa16(sb + (uint32_t)(row * PAD + lds * 4) * 4u,
                  W + (size_t)(n0 + row) * DD + kk + lds * 4);
        }
        CP_COMMIT();
    };

    load_stage(0, 0);
    load_stage(1, 1);

    for (int kt = 0; kt < NKT; kt++) {
        CP_WAIT(STAGES - 2);
        __syncthreads();

        const int s = kt % STAGES;
        const uint32_t* sA = reinterpret_cast<const uint32_t*>(smem + s * STAGE_FLOATS);
        const uint32_t* sB = sA + A_ST_FLOATS;

#pragma unroll
        for (int ks = 0; ks < BK; ks += 8) {
            // A fragments: raw tf32 bits, no cvt on the critical path
            uint32_t afr[4][4];
#pragma unroll
            for (int mt = 0; mt < 4; mt++) {
                const uint32_t* ap = sA + (wm + mt * 16 + g) * PAD + ks + t4;
                afr[mt][0] = ap[0];
                afr[mt][1] = ap[8 * PAD];
                afr[mt][2] = ap[4];
                afr[mt][3] = ap[8 * PAD + 4];
            }
            uint32_t bfr[4][2];
#pragma unroll
            for (int nt = 0; nt < 4; nt++) {
                const uint32_t* bp = sB + (wn + nt * 8 + g) * PAD + ks + t4;
                bfr[nt][0] = bp[0];
                bfr[nt][1] = bp[4];
            }
#pragma unroll
            for (int mt = 0; mt < 4; mt++) {
#pragma unroll
                for (int nt = 0; nt < 4; nt++) {
                    asm volatile(
                        "mma.sync.aligned.m16n8k8.row.col.f32.tf32.tf32.f32 "
                        "{%0,%1,%2,%3}, {%4,%5,%6,%7}, {%8,%9}, {%0,%1,%2,%3};"
                        : "+f"(acc[mt][nt][0]), "+f"(acc[mt][nt][1]),
                          "+f"(acc[mt][nt][2]), "+f"(acc[mt][nt][3])
                        : "r"(afr[mt][0]), "r"(afr[mt][1]),
                          "r"(afr[mt][2]), "r"(afr[mt][3]),
                          "r"(bfr[nt][0]), "r"(bfr[nt][1]));
                }
            }
        }
        __syncthreads();

        if (kt + STAGES - 1 < NKT)
            load_stage(kt + STAGES - 1, (kt + STAGES - 1) % STAGES);
        else
            CP_COMMIT();   // keep group count consistent
    }

    // Epilogue: bias + sigmoid -> g_lam (float2 stores)
#pragma unroll
    for (int mt = 0; mt < 4; mt++) {
#pragma unroll
        for (int half = 0; half < 2; half++) {
            const int row = m0 + wm + mt * 16 + g + half * 8;
            float* dst = g_lam + (size_t)row * DD;
#pragma unroll
            for (int nt = 0; nt < 4; nt++) {
                const int col = n0 + wn + nt * 8 + t4 * 2;
                float2 v;
                v.x = sigmoidf_fast(acc[mt][nt][2 * half + 0] + __ldg(bias + col));
                v.y = sigmoidf_fast(acc[mt][nt][2 * half + 1] + __ldg(bias + col + 1));
                *reinterpret_cast<float2*>(dst + col) = v;
            }
        }
    }
}

// ---------------- chunked 2-phase scan (at DRAM roofline) -------------------
#define SC_CHUNKS 32
#define SC_L (KSEQ / SC_CHUNKS)   // 128
__global__ __launch_bounds__(1024)
void scan_kernel(const float* __restrict__ x, float* __restrict__ out) {
    __shared__ float sP[SC_CHUNKS][33];
    __shared__ float sQ[SC_CHUNKS][33];
    const int lane = threadIdx.x & 31;
    const int ck   = threadIdx.x >> 5;
    const int ch   = blockIdx.x * 32 + lane;
    const int b    = ch >> 11;
    const int d    = ch & (DD - 1);
    const size_t base = ((size_t)b * KSEQ + (size_t)ck * SC_L) * DD + d;

    float s = 0.0f, p = 1.0f;
    {
        size_t idx = base;
#pragma unroll 4
        for (int j = 0; j < SC_L; j++) {
            float lm = __ldg(g_lam + idx);
            float u  = __ldg(x + idx);
            s = fmaf(lm, s - u, u);
            p *= lm;
            idx += DD;
        }
    }
    sP[ck][lane] = p;
    sQ[ck][lane] = s;
    __syncthreads();

    float carry = 0.0f;
    for (int j = 0; j < ck; j++) carry = fmaf(sP[j][lane], carry, sQ[j][lane]);

    {
        size_t idx = base;
        float ss = carry;
#pragma unroll 4
        for (int j = 0; j < SC_L; j++) {
            float lm = __ldg(g_lam + idx);
            float u  = __ldg(x + idx);
            ss = fmaf(lm, ss - u, u);
            out[idx] = ss;
            idx += DD;
        }
    }
}

// ---------------------------------------------------------------------------
extern "C" void kernel_launch(void* const* d_in, const int* in_sizes, int n_in,
                              void* d_out, int out_size) {
    const float* x    = (const float*)d_in[0];   // [B,K,D]
    const float* W    = (const float*)d_in[1];   // [D,D]
    const float* bias = (const float*)d_in[2];   // [D]
    float* out = (float*)d_out;                  // [B,K,D]

    cudaFuncSetAttribute(gemm_sigmoid_kernel,
                         cudaFuncAttributeMaxDynamicSharedMemorySize, GEMM_SMEM);

    round_kernel<<<4096, 256>>>(x, g_xr, (M_TOTAL * DD) / 4);
    round_kernel<<<1024, 256>>>(W, g_wr, (DD * DD) / 4);

    dim3 ggrid(DD / BN, M_TOTAL / Bb);           // (16, 128)
    gemm_sigmoid_kernel<<<ggrid, GEMM_THREADS, GEMM_SMEM>>>(g_xr, g_wr, bias);

    scan_kernel<<<(BB * DD) / 32, 1024>>>(x, out);
}

// round 13
// speedup vs baseline: 30.9074x; 30.9074x over previous
#include <cuda_runtime.h>
#include <cuda_fp16.h>
#include <cstdint>
#include <cstddef>

// Problem dims (fixed)
#define BB 4
#define KSEQ 4096
#define DD 2048
#define M_TOTAL (BB * KSEQ)   // 16384

// Scratch: lam only (WRITTEN by STG, READ by LDG — both proven full-speed).
// HARD RULE (R7/R8/R9/R11): never cp.async FROM __device__ scratch (~40x slow).
__device__ float g_lam[(size_t)M_TOTAL * DD];   // 128 MB

// ---------------------------------------------------------------------------
// GEMM + bias + sigmoid via fp16 mma.sync m16n8k16 (f32 accumulate), fed
// DIRECTLY from d_in via cp.async (fp32 in smem), converted to f16x2 in
// registers at fragment-load time.  R5 skeleton: block 128x128x32, 256 thr
// (8 warps 2x4), warp tile 64x32, 3-stage cp.async, PAD=36 rows.
//   g_lam[m,e] = sigmoid( sum_d x[m,d] * W[e,d] + b[e] )
// ---------------------------------------------------------------------------
#define Bb 128            // block M
#define BN 128            // block N
#define BK 32             // block K (fp32 elements)
#define STAGES 3
#define PAD 36            // floats per smem row
#define A_ST_FLOATS (Bb * PAD)
#define B_ST_FLOATS (BN * PAD)
#define STAGE_FLOATS (A_ST_FLOATS + B_ST_FLOATS)
#define GEMM_SMEM (STAGES * STAGE_FLOATS * 4)     // 110592 B
#define GEMM_THREADS 256

__device__ __forceinline__ uint32_t smem_u32(const void* p) {
    uint32_t a;
    asm("{ .reg .u64 t; cvta.to.shared.u64 t, %1; cvt.u32.u64 %0, t; }" : "=r"(a) : "l"(p));
    return a;
}
__device__ __forceinline__ void cpa16(uint32_t dst, const void* src) {
    asm volatile("cp.async.cg.shared.global [%0], [%1], 16;" :: "r"(dst), "l"(src) : "memory");
}
#define CP_COMMIT() asm volatile("cp.async.commit_group;" ::: "memory")
#define CP_WAIT(n)  asm volatile("cp.async.wait_group %0;" :: "n"(n) : "memory")

// pack two fp32 -> f16x2 (lo = first/even-k element, hi = second)
__device__ __forceinline__ uint32_t pack_f16x2(float lo, float hi) {
    uint32_t r;
    asm("cvt.rn.f16x2.f32 %0, %1, %2;" : "=r"(r) : "f"(hi), "f"(lo));
    return r;
}
__device__ __forceinline__ float sigmoidf_fast(float z) {
    return 1.0f / (1.0f + __expf(-z));
}

__global__ __launch_bounds__(GEMM_THREADS, 2)
void gemm_sigmoid_kernel(const float* __restrict__ A,      // x [M, D] from d_in
                         const float* __restrict__ W,      // W [E, D] from d_in
                         const float* __restrict__ bias) {
    extern __shared__ float smem[];
    const int tid  = threadIdx.x;
    const int warp = tid >> 5;
    const int lane = tid & 31;
    const int m0   = blockIdx.y * Bb;
    const int n0   = blockIdx.x * BN;
    const int wm   = (warp >> 2) * 64;     // 2 warp-rows
    const int wn   = (warp & 3) * 32;      // 4 warp-cols
    const int g    = lane >> 2;            // 0..7
    const int t4   = lane & 3;             // 0..3

    const int ldr = tid >> 3;              // cp.async row 0..31
    const int lds = tid & 7;               // 16B segment 0..7

    const uint32_t smem_base = smem_u32(smem);

    float acc[4][4][4];
#pragma unroll
    for (int i = 0; i < 4; i++)
#pragma unroll
        for (int j = 0; j < 4; j++)
#pragma unroll
            for (int c = 0; c < 4; c++) acc[i][j][c] = 0.0f;

    const int NKT = DD / BK;   // 64 chunks

    auto load_stage = [&](int kt, int s) {
        const int kk = kt * BK;
        const uint32_t sa = smem_base + (uint32_t)(s * STAGE_FLOATS) * 4u;
        const uint32_t sb = sa + (uint32_t)A_ST_FLOATS * 4u;
#pragma unroll
        for (int i = 0; i < 4; i++) {
            int row = i * 32 + ldr;        // 0..127
            cpa16(sa + (uint32_t)(row * PAD + lds * 4) * 4u,
                  A + (size_t)(m0 + row) * DD + kk + lds * 4);
        }
#pragma unroll
        for (int i = 0; i < 4; i++) {
            int row = i * 32 + ldr;
            cpa16(sb + (uint32_t)(row * PAD + lds * 4) * 4u,
                  W + (size_t)(n0 + row) * DD + kk + lds * 4);
        }
        CP_COMMIT();
    };

    load_stage(0, 0);
    load_stage(1, 1);

    for (int kt = 0; kt < NKT; kt++) {
        CP_WAIT(STAGES - 2);
        __syncthreads();

        const int s = kt % STAGES;
        const float* sA = smem + s * STAGE_FLOATS;
        const float* sB = sA + A_ST_FLOATS;

#pragma unroll
        for (int ks = 0; ks < BK; ks += 16) {          // 2 k16 steps per chunk
            // A fragments: per mt, rows g/g+8, k = 2t4(+1) and 2t4+8(+9)
            uint32_t afr[4][4];
#pragma unroll
            for (int mt = 0; mt < 4; mt++) {
                const float* ap = sA + (wm + mt * 16 + g) * PAD + ks + 2 * t4;
                float2 p0 = *reinterpret_cast<const float2*>(ap);
                float2 p1 = *reinterpret_cast<const float2*>(ap + 8 * PAD);
                float2 p2 = *reinterpret_cast<const float2*>(ap + 8);
                float2 p3 = *reinterpret_cast<const float2*>(ap + 8 * PAD + 8);
                afr[mt][0] = pack_f16x2(p0.x, p0.y);
                afr[mt][1] = pack_f16x2(p1.x, p1.y);
                afr[mt][2] = pack_f16x2(p2.x, p2.y);
                afr[mt][3] = pack_f16x2(p3.x, p3.y);
            }
            // B fragments: per nt, col g, k = 2t4(+1) and 2t4+8(+9)
            uint32_t bfr[4][2];
#pragma unroll
            for (int nt = 0; nt < 4; nt++) {
                const float* bp = sB + (wn + nt * 8 + g) * PAD + ks + 2 * t4;
                float2 q0 = *reinterpret_cast<const float2*>(bp);
                float2 q1 = *reinterpret_cast<const float2*>(bp + 8);
                bfr[nt][0] = pack_f16x2(q0.x, q0.y);
                bfr[nt][1] = pack_f16x2(q1.x, q1.y);
            }
#pragma unroll
            for (int mt = 0; mt < 4; mt++) {
#pragma unroll
                for (int nt = 0; nt < 4; nt++) {
                    asm volatile(
                        "mma.sync.aligned.m16n8k16.row.col.f32.f16.f16.f32 "
                        "{%0,%1,%2,%3}, {%4,%5,%6,%7}, {%8,%9}, {%0,%1,%2,%3};"
                        : "+f"(acc[mt][nt][0]), "+f"(acc[mt][nt][1]),
                          "+f"(acc[mt][nt][2]), "+f"(acc[mt][nt][3])
                        : "r"(afr[mt][0]), "r"(afr[mt][1]),
                          "r"(afr[mt][2]), "r"(afr[mt][3]),
                          "r"(bfr[nt][0]), "r"(bfr[nt][1]));
                }
            }
        }
        __syncthreads();

        if (kt + STAGES - 1 < NKT)
            load_stage(kt + STAGES - 1, (kt + STAGES - 1) % STAGES);
        else
            CP_COMMIT();   // keep group count consistent
    }

    // Epilogue: bias + sigmoid -> g_lam (float2 stores; STG to scratch is fast)
#pragma unroll
    for (int mt = 0; mt < 4; mt++) {
#pragma unroll
        for (int half = 0; half < 2; half++) {
            const int row = m0 + wm + mt * 16 + g + half * 8;
            float* dst = g_lam + (size_t)row * DD;
#pragma unroll
            for (int nt = 0; nt < 4; nt++) {
                const int col = n0 + wn + nt * 8 + t4 * 2;
                float2 v;
                v.x = sigmoidf_fast(acc[mt][nt][2 * half + 0] + __ldg(bias + col));
                v.y = sigmoidf_fast(acc[mt][nt][2 * half + 1] + __ldg(bias + col + 1));
                *reinterpret_cast<float2*>(dst + col) = v;
            }
        }
    }
}

// ---------------- chunked 2-phase scan (at DRAM roofline) -------------------
#define SC_CHUNKS 32
#define SC_L (KSEQ / SC_CHUNKS)   // 128
__global__ __launch_bounds__(1024)
void scan_kernel(const float* __restrict__ x, float* __restrict__ out) {
    __shared__ float sP[SC_CHUNKS][33];
    __shared__ float sQ[SC_CHUNKS][33];
    const int lane = threadIdx.x & 31;
    const int ck   = threadIdx.x >> 5;
    const int ch   = blockIdx.x * 32 + lane;
    const int b    = ch >> 11;
    const int d    = ch & (DD - 1);
    const size_t base = ((size_t)b * KSEQ + (size_t)ck * SC_L) * DD + d;

    float s = 0.0f, p = 1.0f;
    {
        size_t idx = base;
#pragma unroll 4
        for (int j = 0; j < SC_L; j++) {
            float lm = __ldg(g_lam + idx);
            float u  = __ldg(x + idx);
            s = fmaf(lm, s - u, u);
            p *= lm;
            idx += DD;
        }
    }
    sP[ck][lane] = p;
    sQ[ck][lane] = s;
    __syncthreads();

    float carry = 0.0f;
    for (int j = 0; j < ck; j++) carry = fmaf(sP[j][lane], carry, sQ[j][lane]);

    {
        size_t idx = base;
        float ss = carry;
#pragma unroll 4
        for (int j = 0; j < SC_L; j++) {
            float lm = __ldg(g_lam + idx);
            float u  = __ldg(x + idx);
            ss = fmaf(lm, ss - u, u);
            out[idx] = ss;
            idx += DD;
        }
    }
}

// ---------------------------------------------------------------------------
extern "C" void kernel_launch(void* const* d_in, const int* in_sizes, int n_in,
                              void* d_out, int out_size) {
    const float* x    = (const float*)d_in[0];   // [B,K,D]
    const float* W    = (const float*)d_in[1];   // [D,D]
    const float* bias = (const float*)d_in[2];   // [D]
    float* out = (float*)d_out;                  // [B,K,D]

    cudaFuncSetAttribute(gemm_sigmoid_kernel,
                         cudaFuncAttributeMaxDynamicSharedMemorySize, GEMM_SMEM);

    dim3 ggrid(DD / BN, M_TOTAL / Bb);           // (16, 128)
    gemm_sigmoid_kernel<<<ggrid, GEMM_THREADS, GEMM_SMEM>>>(x, W, bias);

    scan_kernel<<<(BB * DD) / 32, 1024>>>(x, out);
}

// round 14
// speedup vs baseline: 31.4064x; 1.0161x over previous
#include <cuda_runtime.h>
#include <cstdint>
#include <cstddef>

// Problem dims (fixed)
#define BB 4
#define KSEQ 4096
#define DD 2048
#define M_TOTAL (BB * KSEQ)   // 16384

// Scratch (__device__ globals). RULE: never cp.async FROM these (~40x slow);
// LDG/STG/atomics are full-speed.
__device__ float g_lam[(size_t)M_TOTAL * DD];   // 128 MB

// Lookback publication arrays: 8192 tasks x 32 lanes
#define N_TASKS 8192
__device__ float g_P[N_TASKS * 32];
__device__ float g_Q[N_TASKS * 32];
__device__ float g_S[N_TASKS * 32];
__device__ int   g_flag[N_TASKS];               // 0 none / 1 partial / 2 full

// ---------------------------------------------------------------------------
// GEMM + bias + sigmoid via tf32 mma.sync m16n8k8 — byte-exact R5 config
// (measured 885us GEMM; the legacy-mma hw floor ~155 TF/s on this toolchain).
// Block 128x128x32, 256 thr (8 warps 2x4), warp 64x32, 3-stage cp.async,
// PAD=36 conflict-free scalar LDS, launch_bounds(256,2).
// ---------------------------------------------------------------------------
#define Bb 128
#define BN 128
#define BK 32
#define STAGES 3
#define PAD 36
#define A_ST_FLOATS (Bb * PAD)
#define B_ST_FLOATS (BN * PAD)
#define STAGE_FLOATS (A_ST_FLOATS + B_ST_FLOATS)
#define GEMM_SMEM (STAGES * STAGE_FLOATS * 4)     // 110592 B
#define GEMM_THREADS 256

__device__ __forceinline__ uint32_t smem_u32(const void* p) {
    uint32_t a;
    asm("{ .reg .u64 t; cvta.to.shared.u64 t, %1; cvt.u32.u64 %0, t; }" : "=r"(a) : "l"(p));
    return a;
}
__device__ __forceinline__ void cpa16(uint32_t dst, const void* src) {
    asm volatile("cp.async.cg.shared.global [%0], [%1], 16;" :: "r"(dst), "l"(src) : "memory");
}
#define CP_COMMIT() asm volatile("cp.async.commit_group;" ::: "memory")
#define CP_WAIT(n)  asm volatile("cp.async.wait_group %0;" :: "n"(n) : "memory")

__device__ __forceinline__ uint32_t f32_to_tf32(float v) {
    uint32_t r;
    asm("cvt.rna.tf32.f32 %0, %1;" : "=r"(r) : "f"(v));
    return r;
}
__device__ __forceinline__ float sigmoidf_fast(float z) {
    return 1.0f / (1.0f + __expf(-z));
}

__global__ __launch_bounds__(GEMM_THREADS, 2)
void gemm_sigmoid_kernel(const float* __restrict__ A,      // x [M, D]
                         const float* __restrict__ W,      // W [E, D]
                         const float* __restrict__ bias) {
    extern __shared__ float smem[];
    const int tid  = threadIdx.x;
    const int warp = tid >> 5;
    const int lane = tid & 31;
    const int m0   = blockIdx.y * Bb;
    const int n0   = blockIdx.x * BN;
    const int wm   = (warp >> 2) * 64;
    const int wn   = (warp & 3) * 32;
    const int g    = lane >> 2;
    const int t4   = lane & 3;

    const int ldr = tid >> 3;
    const int lds = tid & 7;

    const uint32_t smem_base = smem_u32(smem);

    float acc[4][4][4];
#pragma unroll
    for (int i = 0; i < 4; i++)
#pragma unroll
        for (int j = 0; j < 4; j++)
#pragma unroll
            for (int c = 0; c < 4; c++) acc[i][j][c] = 0.0f;

    const int NKT = DD / BK;

    auto load_stage = [&](int kt, int s) {
        const int kk = kt * BK;
        const uint32_t sa = smem_base + (uint32_t)(s * STAGE_FLOATS) * 4u;
        const uint32_t sb = sa + (uint32_t)A_ST_FLOATS * 4u;
#pragma unroll
        for (int i = 0; i < 4; i++) {
            int row = i * 32 + ldr;
            cpa16(sa + (uint32_t)(row * PAD + lds * 4) * 4u,
                  A + (size_t)(m0 + row) * DD + kk + lds * 4);
        }
#pragma unroll
        for (int i = 0; i < 4; i++) {
            int row = i * 32 + ldr;
            cpa16(sb + (uint32_t)(row * PAD + lds * 4) * 4u,
                  W + (size_t)(n0 + row) * DD + kk + lds * 4);
        }
        CP_COMMIT();
    };

    load_stage(0, 0);
    load_stage(1, 1);

    for (int kt = 0; kt < NKT; kt++) {
        CP_WAIT(STAGES - 2);
        __syncthreads();

        const int s = kt % STAGES;
        const float* sA = smem + s * STAGE_FLOATS;
        const float* sB = sA + A_ST_FLOATS;

#pragma unroll
        for (int ks = 0; ks < BK; ks += 8) {
            uint32_t afr[4][4];
#pragma unroll
            for (int mt = 0; mt < 4; mt++) {
                const float* ap = sA + (wm + mt * 16 + g) * PAD + ks + t4;
                afr[mt][0] = f32_to_tf32(ap[0]);
                afr[mt][1] = f32_to_tf32(ap[8 * PAD]);
                afr[mt][2] = f32_to_tf32(ap[4]);
                afr[mt][3] = f32_to_tf32(ap[8 * PAD + 4]);
            }
            uint32_t bfr[4][2];
#pragma unroll
            for (int nt = 0; nt < 4; nt++) {
                const float* bp = sB + (wn + nt * 8 + g) * PAD + ks + t4;
                bfr[nt][0] = f32_to_tf32(bp[0]);
                bfr[nt][1] = f32_to_tf32(bp[4]);
            }
#pragma unroll
            for (int mt = 0; mt < 4; mt++) {
#pragma unroll
                for (int nt = 0; nt < 4; nt++) {
                    asm volatile(
                        "mma.sync.aligned.m16n8k8.row.col.f32.tf32.tf32.f32 "
                        "{%0,%1,%2,%3}, {%4,%5,%6,%7}, {%8,%9}, {%0,%1,%2,%3};"
                        : "+f"(acc[mt][nt][0]), "+f"(acc[mt][nt][1]),
                          "+f"(acc[mt][nt][2]), "+f"(acc[mt][nt][3])
                        : "r"(afr[mt][0]), "r"(afr[mt][1]),
                          "r"(afr[mt][2]), "r"(afr[mt][3]),
                          "r"(bfr[nt][0]), "r"(bfr[nt][1]));
                }
            }
        }
        __syncthreads();

        if (kt + STAGES - 1 < NKT)
            load_stage(kt + STAGES - 1, (kt + STAGES - 1) % STAGES);
        else
            CP_COMMIT();
    }

#pragma unroll
    for (int mt = 0; mt < 4; mt++) {
#pragma unroll
        for (int half = 0; half < 2; half++) {
            const int row = m0 + wm + mt * 16 + g + half * 8;
            float* dst = g_lam + (size_t)row * DD;
#pragma unroll
            for (int nt = 0; nt < 4; nt++) {
                const int col = n0 + wn + nt * 8 + t4 * 2;
                float2 v;
                v.x = sigmoidf_fast(acc[mt][nt][2 * half + 0] + __ldg(bias + col));
                v.y = sigmoidf_fast(acc[mt][nt][2 * half + 1] + __ldg(bias + col + 1));
                *reinterpret_cast<float2*>(dst + col) = v;
            }
        }
    }
}

// ---------------------------------------------------------------------------
// Flag zeroing (graph-replay safe; runs each launch)
// ---------------------------------------------------------------------------
__global__ void zero_flags_kernel() {
    int i = blockIdx.x * blockDim.x + threadIdx.x;
    if (i < N_TASKS) g_flag[i] = 0;
}

// ---------------------------------------------------------------------------
// Single-gmem-pass scan with smem cache + decoupled lookback.
// Task/block = (cs: 32 channels, kcg: 128 k). 4 warps x 32 k each.
// Phase A: read lam+x once -> smem cache + per-warp (P,Q).
// Warp 0: publish partial (block P,Q), look back over predecessors for carry,
// publish full. Phase B: replay from smem with composed carry, write out.
// Gmem: 256 MB read + 128 MB write (vs 640 MB for two-pass).
// ---------------------------------------------------------------------------
#define SCK 128                 // k per block
#define SCW 32                  // k per warp
#define KCGS (KSEQ / SCK)       // 32 chunks per channel strip

__global__ __launch_bounds__(128)
void scan_kernel(const float* __restrict__ x, float* __restrict__ out) {
    __shared__ float2 cache[SCK * 32];          // 32 KB: (lam, u) per (k,ch)
    __shared__ float sP[4][32], sQ[4][32], sCarry[32];

    const int tid  = threadIdx.x;
    const int lane = tid & 31;
    const int w    = tid >> 5;
    const int bx   = blockIdx.x;
    const int cs   = bx >> 5;                   // 0..255 channel strip
    const int kcg  = bx & (KCGS - 1);           // 0..31 k chunk (id-ascending)
    const int ch   = cs * 32 + lane;
    const int b    = ch >> 11;
    const int d    = ch & (DD - 1);
    const int k0   = kcg * SCK + w * SCW;
    const size_t base = ((size_t)b * KSEQ + k0) * DD + d;
    const int cslot = w * SCW * 32 + lane;

    // ---- phase A: load once, cache, local scan + product ----
    float s = 0.0f, p = 1.0f;
#pragma unroll
    for (int j0 = 0; j0 < SCW; j0 += 8) {
        float lm[8], u[8];
#pragma unroll
        for (int j = 0; j < 8; j++) {
            size_t id2 = base + (size_t)(j0 + j) * DD;
            lm[j] = __ldg(g_lam + id2);
            u[j]  = __ldg(x + id2);
        }
#pragma unroll
        for (int j = 0; j < 8; j++) {
            cache[cslot + (j0 + j) * 32] = make_float2(lm[j], u[j]);
            s = fmaf(lm[j], s - u[j], u[j]);
            p *= lm[j];
        }
    }
    sP[w][lane] = p;
    sQ[w][lane] = s;
    __syncthreads();

    // ---- warp 0: publish + lookback ----
    if (w == 0) {
        // block-level (P,Q): compose sub-chunks 0..3
        float v = 0.0f, Pb = 1.0f;
#pragma unroll
        for (int j = 0; j < 4; j++) {
            v  = fmaf(sP[j][lane], v, sQ[j][lane]);
            Pb *= sP[j][lane];
        }
        const int t = bx;
        g_P[t * 32 + lane] = Pb;
        g_Q[t * 32 + lane] = v;
        __threadfence();
        __syncwarp();
        if (lane == 0) *((volatile int*)&g_flag[t]) = 1;   // partial

        // lookback for carry entering this chunk
        float carry = 0.0f;
        if (kcg > 0) {
            float Pacc = 1.0f, Qacc = 0.0f;
            int j = kcg - 1;
            while (true) {
                const int tj = cs * KCGS + j;
                int f;
                do {
                    f = *((volatile int*)&g_flag[tj]);
                    if (f < 1) __nanosleep(100);
                } while (f < 1);
                __threadfence();
                if (f == 2) {
                    float Sj = *((volatile float*)&g_S[tj * 32 + lane]);
                    carry = fmaf(Pacc, Sj, Qacc);
                    break;
                } else {
                    float pj = *((volatile float*)&g_P[tj * 32 + lane]);
                    float qj = *((volatile float*)&g_Q[tj * 32 + lane]);
                    Qacc = fmaf(Pacc, qj, Qacc);
                    Pacc *= pj;
                    if (--j < 0) { carry = Qacc; break; }
                }
            }
        }
        float Sfull = fmaf(Pb, carry, v);
        g_S[t * 32 + lane] = Sfull;
        __threadfence();
        __syncwarp();
        if (lane == 0) *((volatile int*)&g_flag[t]) = 2;   // full
        sCarry[lane] = carry;
    }
    __syncthreads();

    // ---- compose this warp's entry carry ----
    float c = sCarry[lane];
#pragma unroll
    for (int j = 0; j < 4; j++)
        if (j < w) c = fmaf(sP[j][lane], c, sQ[j][lane]);

    // ---- phase B: replay from smem, write out ----
    float ss = c;
#pragma unroll
    for (int j = 0; j < SCW; j++) {
        float2 lu = cache[cslot + j * 32];
        ss = fmaf(lu.x, ss - lu.y, lu.y);
        out[base + (size_t)j * DD] = ss;
    }
}

// ---------------------------------------------------------------------------
extern "C" void kernel_launch(void* const* d_in, const int* in_sizes, int n_in,
                              void* d_out, int out_size) {
    const float* x    = (const float*)d_in[0];   // [B,K,D]
    const float* W    = (const float*)d_in[1];   // [D,D]
    const float* bias = (const float*)d_in[2];   // [D]
    float* out = (float*)d_out;                  // [B,K,D]

    cudaFuncSetAttribute(gemm_sigmoid_kernel,
                         cudaFuncAttributeMaxDynamicSharedMemorySize, GEMM_SMEM);

    zero_flags_kernel<<<(N_TASKS + 255) / 256, 256>>>();

    dim3 ggrid(DD / BN, M_TOTAL / Bb);           // (16, 128)
    gemm_sigmoid_kernel<<<ggrid, GEMM_THREADS, GEMM_SMEM>>>(x, W, bias);

    scan_kernel<<<N_TASKS, 128>>>(x, out);
}

// round 15
// speedup vs baseline: 34.4235x; 1.0961x over previous
#include <cuda_runtime.h>
#include <cstdint>
#include <cstddef>

// Problem dims (fixed)
#define BB 4
#define KSEQ 4096
#define DD 2048
#define M_TOTAL (BB * KSEQ)   // 16384

// Scratch (__device__ globals). RULE: never cp.async FROM these (~40x slow);
// LDG/STG are full-speed.
__device__ float g_lam[(size_t)M_TOTAL * DD];     // 128 MB
// Per-(b, chunk128, channel) scan summaries, written by GEMM epilogue:
// P = prod(lam) over chunk, Q = chunk scan result from s0=0.
__device__ float g_P[(size_t)BB * 32 * DD];       // 1 MB
__device__ float g_Q[(size_t)BB * 32 * DD];       // 1 MB

// ---------------------------------------------------------------------------
// GEMM + bias + sigmoid via tf32 mma.sync m16n8k8 — R5 config (measured
// hardware floor ~155 TF/s legacy-mma): block 128x128x32, 256 thr (8 warps
// 2x4), warp 64x32, 3-stage cp.async, PAD=36 conflict-free scalar LDS.
// NEW: epilogue also computes scan summaries (P,Q) for this (k-chunk,
// channel-tile) — the GEMM tile IS one scan task (128 consecutive k x 128
// channels). lam comes from registers via smem; u comes from x via LDG.
// ---------------------------------------------------------------------------
#define Bb 128
#define BN 128
#define BK 32
#define STAGES 3
#define PAD 36
#define A_ST_FLOATS (Bb * PAD)
#define B_ST_FLOATS (BN * PAD)
#define STAGE_FLOATS (A_ST_FLOATS + B_ST_FLOATS)
#define GEMM_SMEM (STAGES * STAGE_FLOATS * 4)     // 110592 B
#define GEMM_THREADS 256
#define TPAD 129                                  // epilogue tile row pitch

__device__ __forceinline__ uint32_t smem_u32(const void* p) {
    uint32_t a;
    asm("{ .reg .u64 t; cvta.to.shared.u64 t, %1; cvt.u32.u64 %0, t; }" : "=r"(a) : "l"(p));
    return a;
}
__device__ __forceinline__ void cpa16(uint32_t dst, const void* src) {
    asm volatile("cp.async.cg.shared.global [%0], [%1], 16;" :: "r"(dst), "l"(src) : "memory");
}
#define CP_COMMIT() asm volatile("cp.async.commit_group;" ::: "memory")
#define CP_WAIT(n)  asm volatile("cp.async.wait_group %0;" :: "n"(n) : "memory")

__device__ __forceinline__ uint32_t f32_to_tf32(float v) {
    uint32_t r;
    asm("cvt.rna.tf32.f32 %0, %1;" : "=r"(r) : "f"(v));
    return r;
}
__device__ __forceinline__ float sigmoidf_fast(float z) {
    return 1.0f / (1.0f + __expf(-z));
}

__global__ __launch_bounds__(GEMM_THREADS, 2)
void gemm_sigmoid_kernel(const float* __restrict__ A,      // x [M, D]
                         const float* __restrict__ W,      // W [E, D]
                         const float* __restrict__ bias) {
    extern __shared__ float smem[];
    const int tid  = threadIdx.x;
    const int warp = tid >> 5;
    const int lane = tid & 31;
    const int m0   = blockIdx.y * Bb;
    const int n0   = blockIdx.x * BN;
    const int wm   = (warp >> 2) * 64;
    const int wn   = (warp & 3) * 32;
    const int g    = lane >> 2;
    const int t4   = lane & 3;

    const int ldr = tid >> 3;
    const int lds = tid & 7;

    const uint32_t smem_base = smem_u32(smem);

    float acc[4][4][4];
#pragma unroll
    for (int i = 0; i < 4; i++)
#pragma unroll
        for (int j = 0; j < 4; j++)
#pragma unroll
            for (int c = 0; c < 4; c++) acc[i][j][c] = 0.0f;

    const int NKT = DD / BK;

    auto load_stage = [&](int kt, int s) {
        const int kk = kt * BK;
        const uint32_t sa = smem_base + (uint32_t)(s * STAGE_FLOATS) * 4u;
        const uint32_t sb = sa + (uint32_t)A_ST_FLOATS * 4u;
#pragma unroll
        for (int i = 0; i < 4; i++) {
            int row = i * 32 + ldr;
            cpa16(sa + (uint32_t)(row * PAD + lds * 4) * 4u,
                  A + (size_t)(m0 + row) * DD + kk + lds * 4);
        }
#pragma unroll
        for (int i = 0; i < 4; i++) {
            int row = i * 32 + ldr;
            cpa16(sb + (uint32_t)(row * PAD + lds * 4) * 4u,
                  W + (size_t)(n0 + row) * DD + kk + lds * 4);
        }
        CP_COMMIT();
    };

    load_stage(0, 0);
    load_stage(1, 1);

    for (int kt = 0; kt < NKT; kt++) {
        CP_WAIT(STAGES - 2);
        __syncthreads();

        const int s = kt % STAGES;
        const float* sA = smem + s * STAGE_FLOATS;
        const float* sB = sA + A_ST_FLOATS;

#pragma unroll
        for (int ks = 0; ks < BK; ks += 8) {
            uint32_t afr[4][4];
#pragma unroll
            for (int mt = 0; mt < 4; mt++) {
                const float* ap = sA + (wm + mt * 16 + g) * PAD + ks + t4;
                afr[mt][0] = f32_to_tf32(ap[0]);
                afr[mt][1] = f32_to_tf32(ap[8 * PAD]);
                afr[mt][2] = f32_to_tf32(ap[4]);
                afr[mt][3] = f32_to_tf32(ap[8 * PAD + 4]);
            }
            uint32_t bfr[4][2];
#pragma unroll
            for (int nt = 0; nt < 4; nt++) {
                const float* bp = sB + (wn + nt * 8 + g) * PAD + ks + t4;
                bfr[nt][0] = f32_to_tf32(bp[0]);
                bfr[nt][1] = f32_to_tf32(bp[4]);
            }
#pragma unroll
            for (int mt = 0; mt < 4; mt++) {
#pragma unroll
                for (int nt = 0; nt < 4; nt++) {
                    asm volatile(
                        "mma.sync.aligned.m16n8k8.row.col.f32.tf32.tf32.f32 "
                        "{%0,%1,%2,%3}, {%4,%5,%6,%7}, {%8,%9}, {%0,%1,%2,%3};"
                        : "+f"(acc[mt][nt][0]), "+f"(acc[mt][nt][1]),
                          "+f"(acc[mt][nt][2]), "+f"(acc[mt][nt][3])
                        : "r"(afr[mt][0]), "r"(afr[mt][1]),
                          "r"(afr[mt][2]), "r"(afr[mt][3]),
                          "r"(bfr[nt][0]), "r"(bfr[nt][1]));
                }
            }
        }
        __syncthreads();

        if (kt + STAGES - 1 < NKT)
            load_stage(kt + STAGES - 1, (kt + STAGES - 1) % STAGES);
        else
            CP_COMMIT();
    }

    // ---- epilogue 1: bias + sigmoid -> g_lam (gmem) + smem tile ----
    // smem stages are dead after the final __syncthreads; reuse as
    // tile[128][TPAD] (lam, indexed [k-row][channel]) = 66 KB < 110 KB.
    float* tile = smem;
#pragma unroll
    for (int mt = 0; mt < 4; mt++) {
#pragma unroll
        for (int half = 0; half < 2; half++) {
            const int row  = wm + mt * 16 + g + half * 8;   // local m-row
            float* dst = g_lam + (size_t)(m0 + row) * DD;
#pragma unroll
            for (int nt = 0; nt < 4; nt++) {
                const int col = wn + nt * 8 + t4 * 2;       // local channel
                float2 v;
                v.x = sigmoidf_fast(acc[mt][nt][2 * half + 0] + __ldg(bias + n0 + col));
                v.y = sigmoidf_fast(acc[mt][nt][2 * half + 1] + __ldg(bias + n0 + col + 1));
                *reinterpret_cast<float2*>(dst + n0 + col) = v;
                tile[row * TPAD + col]     = v.x;           // scalar STS (alignment)
                tile[row * TPAD + col + 1] = v.y;
            }
        }
    }
    __syncthreads();

    // ---- epilogue 2: per-channel scan summary (P,Q) for this 128-k chunk ----
    // thread: channel e = tid&127, k-half = tid>>7 (64 rows each).
    {
        const int e    = tid & 127;
        const int half = tid >> 7;
        const int b    = m0 >> 12;           // m0 / 4096
        const int kcg  = (m0 >> 7) & 31;     // chunk-of-128 within b
        const int r0   = half * 64;

        float s = 0.0f, p = 1.0f;
#pragma unroll 8
        for (int j = 0; j < 64; j++) {
            float lm = tile[(r0 + j) * TPAD + e];
            float u  = __ldg(A + (size_t)(m0 + r0 + j) * DD + n0 + e);  // x[k, d=e]
            s = fmaf(lm, s - u, u);
            p *= lm;
        }
        // combine halves: ex region after tile (offset 128*TPAD floats)
        float* ex = smem + 128 * TPAD;
        ex[(half * 128 + e) * 2 + 0] = p;
        ex[(half * 128 + e) * 2 + 1] = s;
        __syncthreads();
        if (half == 0) {
            float P0 = p, Q0 = s;
            float P1 = ex[(128 + e) * 2 + 0];
            float Q1 = ex[(128 + e) * 2 + 1];
            const size_t o = ((size_t)b * 32 + kcg) * DD + n0 + e;
            g_P[o] = P0 * P1;
            g_Q[o] = fmaf(P1, Q0, Q1);
        }
    }
}

// ---------------------------------------------------------------------------
// Single-pass scan: carry composed from precomputed (P,Q) — no phase A.
// Block: 32 channels (lane) x 32 chunk-warps (1024 thr); warp ck replays
// chunk ck (128 k) with carry = compose_{j<ck}(P_j, Q_j).
// Gmem: ~33 MB P/Q + 256 MB lam/x + 128 MB write (vs 640 MB two-pass).
// ---------------------------------------------------------------------------
#define SC_CHUNKS 32
#define SC_L (KSEQ / SC_CHUNKS)   // 128
__global__ __launch_bounds__(1024)
void scan_kernel(const float* __restrict__ x, float* __restrict__ out) {
    const int lane = threadIdx.x & 31;
    const int ck   = threadIdx.x >> 5;
    const int ch   = blockIdx.x * 32 + lane;
    const int b    = ch >> 11;
    const int d    = ch & (DD - 1);
    const size_t base = ((size_t)b * KSEQ + (size_t)ck * SC_L) * DD + d;

    // carry entering chunk ck from published summaries
    float carry = 0.0f;
    {
        const float* Pp = g_P + (size_t)b * 32 * DD + d;
        const float* Qp = g_Q + (size_t)b * 32 * DD + d;
        for (int j = 0; j < ck; j++)
            carry = fmaf(__ldg(Pp + (size_t)j * DD), carry, __ldg(Qp + (size_t)j * DD));
    }

    // replay with carry, write out (single gmem pass over lam/x)
    size_t idx = base;
    float ss = carry;
#pragma unroll 4
    for (int j = 0; j < SC_L; j++) {
        float lm = __ldg(g_lam + idx);
        float u  = __ldg(x + idx);
        ss = fmaf(lm, ss - u, u);
        out[idx] = ss;
        idx += DD;
    }
}

// ---------------------------------------------------------------------------
extern "C" void kernel_launch(void* const* d_in, const int* in_sizes, int n_in,
                              void* d_out, int out_size) {
    const float* x    = (const float*)d_in[0];   // [B,K,D]
    const float* W    = (const float*)d_in[1];   // [D,D]
    const float* bias = (const float*)d_in[2];   // [D]
    float* out = (float*)d_out;                  // [B,K,D]

    cudaFuncSetAttribute(gemm_sigmoid_kernel,
                         cudaFuncAttributeMaxDynamicSharedMemorySize, GEMM_SMEM);

    dim3 ggrid(DD / BN, M_TOTAL / Bb);           // (16, 128)
    gemm_sigmoid_kernel<<<ggrid, GEMM_THREADS, GEMM_SMEM>>>(x, W, bias);

    scan_kernel<<<(BB * DD) / 32, 1024>>>(x, out);
}